// round 12
// baseline (speedup 1.0000x reference)
#include <cuda_runtime.h>
#include <cstdint>

// Problem constants
#define RR 4
#define ND 81
#define NB 4
#define NC 128
#define NH 96
#define NW 160

// Tile geometry (proven R4 core)
#define TX 32
#define YB 4
#define PX 4
#define XG 8
#define NDY 9
#define NTHREADS 288
#define CCHUNK 8
#define NCHUNK 16
#define TGT_W 40
#define TGT_H 12
#define TGT_TILE (CCHUNK*TGT_H*TGT_W)    // 3840 floats
#define SRC_TILE (CCHUNK*YB*TX)          // 1024 floats
#define BUF_FLOATS (TGT_TILE + SRC_TILE) // 4864
#define BUF_BYTES (BUF_FLOATS*4)         // 19456
#define SMEM_BYTES (3*BUF_BYTES)         // 58368
#define NQUADS (BUF_FLOATS/4)            // 1216
#define MAXSLOTS 5
#define CBYTES (CCHUNK*NH*NW*4)

// Schedule: 444 blocks (148 SMs x occ 3 = ONE wave, all co-resident).
// Main tiles 0..443 -> block bid. Leftover tiles 444..479 decomposed into
// 576 (tile, 8-channel-chunk) tasks; block bid runs task bid and, if
// bid < 132, task 444+bid. Tasks accumulate via atomicAdd into a region
// zero-initialized by all blocks at kernel start (safe: earliest add is
// after a full main tile, >20us after all zeroing completes).
#define NBLOCKS 444
#define NTASKS 576                       // 36 tiles * 16 chunks
#define ZQ_TOTAL 93312                   // 36*81*4*8 float4s in leftover region

__device__ __forceinline__ int disp_index(int dyv, int dxv) {
    int ay = dyv < 0 ? -dyv : dyv;
    int ax = dxv < 0 ? -dxv : dxv;
    if ((ay | ax) == 0) return 0;
    if (ax == 0) return 1 + (ay - 1) * 20 + (dyv < 0 ? 0 : 1);
    if (ay == 0) return 1 + (ax - 1) * 20 + (dxv < 0 ? 2 : 3);
    int base = 1 + (ay - 1) * 20 + 4 + (ax - 1) * 4;
    if (dyv < 0 && dxv < 0) return base + 0;
    if (dyv > 0 && dxv > 0) return base + 1;
    if (dyv < 0 && dxv > 0) return base + 2;
    return base + 3;
}

__device__ __forceinline__ void cp_async16(uint32_t saddr, const void* gaddr, int sz) {
    asm volatile("cp.async.cg.shared.global [%0], [%1], 16, %2;\n"
                 :: "r"(saddr), "l"(gaddr), "r"(sz));
}
__device__ __forceinline__ void cp_commit() {
    asm volatile("cp.async.commit_group;\n" ::: "memory");
}

__global__ __launch_bounds__(NTHREADS, 3)
void costvol_kernel(const float* __restrict__ src,
                    const float* __restrict__ tgt,
                    float* __restrict__ out) {
    extern __shared__ __align__(16) float sm[];
    const int tid = threadIdx.x;
    const int bid = blockIdx.x;
    const uint32_t smem_base = (uint32_t)__cvta_generic_to_shared(&sm[0]);

    // ---- compute role (fixed) ----
    const int xg   = tid & (XG - 1);
    const int dyi  = (tid >> 3) % NDY;
    const int yr   = tid / (XG * NDY);
    const int dyv  = dyi - RR;
    const int trow = yr + dyi;
    const int t_off = trow * TGT_W + xg * PX;
    const int s_off = TGT_TILE + yr * TX + xg * PX;
    const float inv = 1.0f / 81.0f;

    // ========== Phase A: zero 1/444 of the leftover output region ==========
    {
        int zq = bid + NBLOCKS * tid;        // round-robin float4 index
        if (tid < 211 && zq < ZQ_TOTAL) {
            int lt = zq / 2592;              // 81*4*8
            int r  = zq % 2592;
            int d  = r / 32;
            int r2 = r % 32;
            int ry = r2 / 8;
            int xq = r2 % 8;
            int rem = 84 + lt;               // (444+lt) % 120
            int y = (rem / 5) * YB + ry;
            int x = (rem % 5) * TX + xq * 4;
            float4* p = (float4*)(out + (((size_t)(3 * ND + d) * NH) + y) * NW + x);
            *p = make_float4(0.f, 0.f, 0.f, 0.f);
        }
    }

    // ---- slot-offset builder for a tile at (x0,y0) ----
    auto make_slots = [&](int x0, int y0, uint32_t* goff, uint32_t& flags) {
        flags = 0;
#pragma unroll
        for (int k = 0; k < MAXSLOTS; k++) {
            int idx = tid + k * NTHREADS;
            goff[k] = 0;
            if (idx < NQUADS) {
                if (idx < TGT_TILE / 4) {
                    int cc  = idx / (TGT_H * (TGT_W / 4));
                    int rm  = idx % (TGT_H * (TGT_W / 4));
                    int row = rm / (TGT_W / 4);
                    int xq  = rm % (TGT_W / 4);
                    int gy = y0 + row - RR;
                    int gx = x0 + xq * 4 - RR;
                    bool ok = ((unsigned)gy < NH) && ((unsigned)gx < NW);
                    if (ok) goff[k] = (uint32_t)(((cc * NH + gy) * NW + gx) * 4);
                    flags |= 1u << k;
                    if (ok) flags |= 1u << (k + 8);
                } else {
                    int q   = idx - TGT_TILE / 4;
                    int cc  = q / (YB * TX / 4);
                    int rm  = q % (YB * TX / 4);
                    int ry  = rm / (TX / 4);
                    int xq  = rm % (TX / 4);
                    goff[k] = (uint32_t)(((cc * NH + y0 + ry) * NW + x0 + xq * 4) * 4);
                    flags |= 1u << (k + 8);
                }
            }
        }
    };

    uint32_t goff[MAXSLOTS];
    uint32_t flags;

    auto stage = [&](int bi, const char* srcB, const char* tgtB) {
        const uint32_t bofs = (uint32_t)bi * BUF_BYTES;
#pragma unroll
        for (int k = 0; k < MAXSLOTS; k++) {
            if (k < MAXSLOTS - 1 || tid < NQUADS - (MAXSLOTS - 1) * NTHREADS) {
                const char* base = (flags >> k & 1) ? tgtB : srcB;
                int sz = (flags >> (k + 8) & 1) ? 16 : 0;
                cp_async16(smem_base + bofs + (uint32_t)(tid + k * NTHREADS) * 16,
                           base + goff[k], sz);
                goff[k] += CBYTES;
            }
        }
        cp_commit();
    };

    float acc[NDY][PX];
    auto do_chunk = [&](const float* bp) {
        const float* tb = bp + t_off;
        const float* sb = bp + s_off;
#pragma unroll
        for (int cc = 0; cc < CCHUNK; cc++) {
            float4 s4 = *(const float4*)(sb + cc * (YB * TX));
            const float4* tq = (const float4*)(tb + cc * (TGT_H * TGT_W));
            float4 t0 = tq[0], t1 = tq[1], t2 = tq[2];
            float s[PX] = {s4.x, s4.y, s4.z, s4.w};
            float t[12] = {t0.x, t0.y, t0.z, t0.w,
                           t1.x, t1.y, t1.z, t1.w,
                           t2.x, t2.y, t2.z, t2.w};
#pragma unroll
            for (int dx = 0; dx < NDY; dx++)
#pragma unroll
                for (int p = 0; p < PX; p++)
                    acc[dx][p] = fmaf(s[p], t[dx + p], acc[dx][p]);
        }
    };

    // ================= Phase B: main tile (tile id = bid) =================
    {
        const int b   = bid / 120;
        const int rem = bid % 120;
        const int y0  = (rem / 5) * YB;
        const int x0  = (rem % 5) * TX;

        const char* srcB = (const char*)(src + (size_t)b * NC * NH * NW);
        const char* tgtB = (const char*)(tgt + (size_t)b * NC * NH * NW);

        make_slots(x0, y0, goff, flags);

#pragma unroll
        for (int i = 0; i < NDY; i++)
#pragma unroll
            for (int p = 0; p < PX; p++) acc[i][p] = 0.0f;

        stage(0, srcB, tgtB);
        stage(1, srcB, tgtB);

#pragma unroll 1
        for (int ch = 0; ch < NCHUNK; ch++) {
            if (ch + 2 < NCHUNK)
                asm volatile("cp.async.wait_group 1;\n" ::: "memory");
            else
                asm volatile("cp.async.wait_group 0;\n" ::: "memory");
            __syncthreads();

            do_chunk(sm + (ch % 3) * BUF_FLOATS);

            if (ch + 2 < NCHUNK)
                stage((ch + 2) % 3, srcB, tgtB);
        }

        const int y = y0 + yr;
#pragma unroll
        for (int dx = 0; dx < NDY; dx++) {
            int d = disp_index(dyv, dx - RR);
            float* o = out + ((((size_t)b * ND + d) * NH) + y) * NW + x0 + xg * PX;
            float4 v = make_float4(acc[dx][0] * inv, acc[dx][1] * inv,
                                   acc[dx][2] * inv, acc[dx][3] * inv);
            *(float4*)o = v;
        }
    }

    // ======= Phase C: 1-2 leftover chunk-tasks (atomic accumulation) =======
#pragma unroll 1
    for (int t = 0; t < 2; t++) {
        if (t == 1 && bid >= NTASKS - NBLOCKS) break;   // only bid<132 get a 2nd
        const int task  = bid + t * NBLOCKS;            // 0..575
        const int lt    = task >> 4;                    // leftover tile 0..35
        const int chunk = task & 15;                    // 8-channel chunk

        const int rem = 84 + lt;                        // (444+lt)%120, b=3
        const int y0  = (rem / 5) * YB;
        const int x0  = (rem % 5) * TX;

        const char* srcB = (const char*)(src + (size_t)3 * NC * NH * NW)
                           + (size_t)chunk * CBYTES;
        const char* tgtB = (const char*)(tgt + (size_t)3 * NC * NH * NW)
                           + (size_t)chunk * CBYTES;

        make_slots(x0, y0, goff, flags);

        __syncthreads();           // prior phase done reading smem buffer 0
        stage(0, srcB, tgtB);
        asm volatile("cp.async.wait_group 0;\n" ::: "memory");
        __syncthreads();

#pragma unroll
        for (int i = 0; i < NDY; i++)
#pragma unroll
            for (int p = 0; p < PX; p++) acc[i][p] = 0.0f;

        do_chunk(sm);

        const int y = y0 + yr;
#pragma unroll
        for (int dx = 0; dx < NDY; dx++) {
            int d = disp_index(dyv, dx - RR);
            float* o = out + (((size_t)(3 * ND + d) * NH) + y) * NW + x0 + xg * PX;
#pragma unroll
            for (int p = 0; p < PX; p++)
                atomicAdd(o + p, acc[dx][p] * inv);
        }
    }
}

extern "C" void kernel_launch(void* const* d_in, const int* in_sizes, int n_in,
                              void* d_out, int out_size) {
    const float* src = (const float*)d_in[0];
    const float* tgt = (const float*)d_in[1];
    float* out = (float*)d_out;

    cudaFuncSetAttribute(costvol_kernel,
                         cudaFuncAttributeMaxDynamicSharedMemorySize, SMEM_BYTES);

    costvol_kernel<<<NBLOCKS, NTHREADS, SMEM_BYTES>>>(src, tgt, out);
}

// round 13
// speedup vs baseline: 1.1143x; 1.1143x over previous
#include <cuda_runtime.h>
#include <cstdint>

// Problem constants
#define RR 4
#define ND 81
#define NB 4
#define NC 128
#define NH 96
#define NW 160

// Tile geometry (proven R4/R9 core)
#define TX 32
#define YB 4
#define PX 4
#define XG 8
#define NDY 9
#define NTHREADS 288
#define CCHUNK 8
#define NCHUNK 16
#define TGT_W 40
#define TGT_H 12
#define TGT_TILE (CCHUNK*TGT_H*TGT_W)    // 3840 floats
#define SRC_TILE (CCHUNK*YB*TX)          // 1024 floats
#define BUF_FLOATS (TGT_TILE + SRC_TILE) // 4864
#define BUF_BYTES (BUF_FLOATS*4)         // 19456
#define SMEM_BYTES (3*BUF_BYTES)         // 58368
#define NQUADS (BUF_FLOATS/4)            // 1216
#define MAXSLOTS 5
#define CBYTES (CCHUNK*NH*NW*4)

// k1: 444 full tiles = 148 SMs x occ 3, one perfect wave. Also zeroes the
// leftover output region (tiles 444..479) at start.
// k2: 288 blocks; block = (leftover tile lt 0..35, 16-channel group qc 0..7),
// 2 chunks each, results merged by atomicAdd (8 contributors/element).
#define K1_TILES 444
#define K2_BLOCKS 288
#define ZQ_TOTAL 93312        // 36 tiles * 81 d * 4 rows * 8 quads (float4s)
#define SMEM2_BYTES (2*BUF_BYTES)

__device__ __forceinline__ int disp_index(int dyv, int dxv) {
    int ay = dyv < 0 ? -dyv : dyv;
    int ax = dxv < 0 ? -dxv : dxv;
    if ((ay | ax) == 0) return 0;
    if (ax == 0) return 1 + (ay - 1) * 20 + (dyv < 0 ? 0 : 1);
    if (ay == 0) return 1 + (ax - 1) * 20 + (dxv < 0 ? 2 : 3);
    int base = 1 + (ay - 1) * 20 + 4 + (ax - 1) * 4;
    if (dyv < 0 && dxv < 0) return base + 0;
    if (dyv > 0 && dxv > 0) return base + 1;
    if (dyv < 0 && dxv > 0) return base + 2;
    return base + 3;
}

__device__ __forceinline__ void cp_async16(uint32_t saddr, const void* gaddr, int sz) {
    asm volatile("cp.async.cg.shared.global [%0], [%1], 16, %2;\n"
                 :: "r"(saddr), "l"(gaddr), "r"(sz));
}
__device__ __forceinline__ void cp_commit() {
    asm volatile("cp.async.commit_group;\n" ::: "memory");
}

// shared slot-offset builder (full-tile layout)
__device__ __forceinline__ void make_slots(int tid, int x0, int y0,
                                           uint32_t* goff, uint32_t& flags) {
    flags = 0;
#pragma unroll
    for (int k = 0; k < MAXSLOTS; k++) {
        int idx = tid + k * NTHREADS;
        goff[k] = 0;
        if (idx < NQUADS) {
            if (idx < TGT_TILE / 4) {
                int cc  = idx / (TGT_H * (TGT_W / 4));
                int rm  = idx % (TGT_H * (TGT_W / 4));
                int row = rm / (TGT_W / 4);
                int xq  = rm % (TGT_W / 4);
                int gy = y0 + row - RR;
                int gx = x0 + xq * 4 - RR;
                bool ok = ((unsigned)gy < NH) && ((unsigned)gx < NW);
                if (ok) goff[k] = (uint32_t)(((cc * NH + gy) * NW + gx) * 4);
                flags |= 1u << k;
                if (ok) flags |= 1u << (k + 8);
            } else {
                int q   = idx - TGT_TILE / 4;
                int cc  = q / (YB * TX / 4);
                int rm  = q % (YB * TX / 4);
                int ry  = rm / (TX / 4);
                int xq  = rm % (TX / 4);
                goff[k] = (uint32_t)(((cc * NH + y0 + ry) * NW + x0 + xq * 4) * 4);
                flags |= 1u << (k + 8);
            }
        }
    }
}

// ===================== Kernel 1: 444 full tiles + zeroing =====================
__global__ __launch_bounds__(NTHREADS, 3)
void costvol_k1(const float* __restrict__ src,
                const float* __restrict__ tgt,
                float* __restrict__ out) {
    extern __shared__ __align__(16) float sm[];
    const int tid = threadIdx.x;
    const int bid = blockIdx.x;
    const uint32_t smem_base = (uint32_t)__cvta_generic_to_shared(&sm[0]);

    // Phase A: zero 1/444 of the leftover output region (k2 atomicAdds there)
    {
        int zq = bid + K1_TILES * tid;
        if (tid < 211 && zq < ZQ_TOTAL) {
            int lt = zq / 2592;              // 81*4*8
            int r  = zq % 2592;
            int d  = r / 32;
            int r2 = r % 32;
            int ry = r2 / 8;
            int xq = r2 % 8;
            int rem = 84 + lt;               // (444+lt) % 120, b=3
            int y = (rem / 5) * YB + ry;
            int x = (rem % 5) * TX + xq * 4;
            float4* p = (float4*)(out + (((size_t)(3 * ND + d) * NH) + y) * NW + x);
            *p = make_float4(0.f, 0.f, 0.f, 0.f);
        }
    }

    const int b   = bid / 120;
    const int rem = bid % 120;
    const int y0  = (rem / 5) * YB;
    const int x0  = (rem % 5) * TX;

    const char* srcB = (const char*)(src + (size_t)b * NC * NH * NW);
    const char* tgtB = (const char*)(tgt + (size_t)b * NC * NH * NW);

    uint32_t goff[MAXSLOTS];
    uint32_t flags;
    make_slots(tid, x0, y0, goff, flags);

    const int xg   = tid & (XG - 1);
    const int dyi  = (tid >> 3) % NDY;
    const int yr   = tid / (XG * NDY);
    const int dyv  = dyi - RR;
    const int trow = yr + dyi;
    const int t_off = trow * TGT_W + xg * PX;
    const int s_off = TGT_TILE + yr * TX + xg * PX;

    float acc[NDY][PX];
#pragma unroll
    for (int i = 0; i < NDY; i++)
#pragma unroll
        for (int p = 0; p < PX; p++) acc[i][p] = 0.0f;

    auto stage = [&](int bi) {
        const uint32_t bofs = (uint32_t)bi * BUF_BYTES;
#pragma unroll
        for (int k = 0; k < MAXSLOTS; k++) {
            if (k < MAXSLOTS - 1 || tid < NQUADS - (MAXSLOTS - 1) * NTHREADS) {
                const char* base = (flags >> k & 1) ? tgtB : srcB;
                int sz = (flags >> (k + 8) & 1) ? 16 : 0;
                cp_async16(smem_base + bofs + (uint32_t)(tid + k * NTHREADS) * 16,
                           base + goff[k], sz);
                goff[k] += CBYTES;
            }
        }
        cp_commit();
    };

    stage(0);
    stage(1);

#pragma unroll 1
    for (int ch = 0; ch < NCHUNK; ch++) {
        if (ch + 2 < NCHUNK)
            asm volatile("cp.async.wait_group 1;\n" ::: "memory");
        else
            asm volatile("cp.async.wait_group 0;\n" ::: "memory");
        __syncthreads();

        const float* bp = sm + (ch % 3) * BUF_FLOATS;
        const float* tb = bp + t_off;
        const float* sb = bp + s_off;
#pragma unroll
        for (int cc = 0; cc < CCHUNK; cc++) {
            float4 s4 = *(const float4*)(sb + cc * (YB * TX));
            const float4* tq = (const float4*)(tb + cc * (TGT_H * TGT_W));
            float4 t0 = tq[0], t1 = tq[1], t2 = tq[2];
            float s[PX] = {s4.x, s4.y, s4.z, s4.w};
            float t[12] = {t0.x, t0.y, t0.z, t0.w,
                           t1.x, t1.y, t1.z, t1.w,
                           t2.x, t2.y, t2.z, t2.w};
#pragma unroll
            for (int dx = 0; dx < NDY; dx++)
#pragma unroll
                for (int p = 0; p < PX; p++)
                    acc[dx][p] = fmaf(s[p], t[dx + p], acc[dx][p]);
        }

        if (ch + 2 < NCHUNK)
            stage((ch + 2) % 3);
    }

    const float inv = 1.0f / 81.0f;
    const int y = y0 + yr;
#pragma unroll
    for (int dx = 0; dx < NDY; dx++) {
        int d = disp_index(dyv, dx - RR);
        float* o = out + ((((size_t)b * ND + d) * NH) + y) * NW + x0 + xg * PX;
        float4 v = make_float4(acc[dx][0] * inv, acc[dx][1] * inv,
                               acc[dx][2] * inv, acc[dx][3] * inv);
        *(float4*)o = v;
    }
}

// ===== Kernel 2: 288 blocks, (leftover tile, 16-channel) tasks, atomics =====
__global__ __launch_bounds__(NTHREADS, 3)
void costvol_k2(const float* __restrict__ src,
                const float* __restrict__ tgt,
                float* __restrict__ out) {
    extern __shared__ __align__(16) float sm[];   // 2 buffers
    const int tid = threadIdx.x;
    const int lt  = blockIdx.x >> 3;              // 0..35
    const int qc  = blockIdx.x & 7;               // 16-channel group

    const int rem = 84 + lt;                      // (444+lt)%120, b=3
    const int y0  = (rem / 5) * YB;
    const int x0  = (rem % 5) * TX;

    const char* srcB = (const char*)(src + (size_t)3 * NC * NH * NW)
                       + (size_t)qc * 2 * CBYTES;
    const char* tgtB = (const char*)(tgt + (size_t)3 * NC * NH * NW)
                       + (size_t)qc * 2 * CBYTES;

    uint32_t goff[MAXSLOTS];
    uint32_t flags;
    make_slots(tid, x0, y0, goff, flags);

    const uint32_t smem_base = (uint32_t)__cvta_generic_to_shared(&sm[0]);

    const int xg   = tid & (XG - 1);
    const int dyi  = (tid >> 3) % NDY;
    const int yr   = tid / (XG * NDY);
    const int dyv  = dyi - RR;
    const int trow = yr + dyi;
    const int t_off = trow * TGT_W + xg * PX;
    const int s_off = TGT_TILE + yr * TX + xg * PX;

    float acc[NDY][PX];
#pragma unroll
    for (int i = 0; i < NDY; i++)
#pragma unroll
        for (int p = 0; p < PX; p++) acc[i][p] = 0.0f;

    auto stage = [&](int bi) {
        const uint32_t bofs = (uint32_t)bi * BUF_BYTES;
#pragma unroll
        for (int k = 0; k < MAXSLOTS; k++) {
            if (k < MAXSLOTS - 1 || tid < NQUADS - (MAXSLOTS - 1) * NTHREADS) {
                const char* base = (flags >> k & 1) ? tgtB : srcB;
                int sz = (flags >> (k + 8) & 1) ? 16 : 0;
                cp_async16(smem_base + bofs + (uint32_t)(tid + k * NTHREADS) * 16,
                           base + goff[k], sz);
                goff[k] += CBYTES;
            }
        }
        cp_commit();
    };

    stage(0);   // chunk 0
    stage(1);   // chunk 1

#pragma unroll
    for (int ch = 0; ch < 2; ch++) {
        if (ch == 0)
            asm volatile("cp.async.wait_group 1;\n" ::: "memory");
        else
            asm volatile("cp.async.wait_group 0;\n" ::: "memory");
        __syncthreads();

        const float* bp = sm + ch * BUF_FLOATS;
        const float* tb = bp + t_off;
        const float* sb = bp + s_off;
#pragma unroll
        for (int cc = 0; cc < CCHUNK; cc++) {
            float4 s4 = *(const float4*)(sb + cc * (YB * TX));
            const float4* tq = (const float4*)(tb + cc * (TGT_H * TGT_W));
            float4 t0 = tq[0], t1 = tq[1], t2 = tq[2];
            float s[PX] = {s4.x, s4.y, s4.z, s4.w};
            float t[12] = {t0.x, t0.y, t0.z, t0.w,
                           t1.x, t1.y, t1.z, t1.w,
                           t2.x, t2.y, t2.z, t2.w};
#pragma unroll
            for (int dx = 0; dx < NDY; dx++)
#pragma unroll
                for (int p = 0; p < PX; p++)
                    acc[dx][p] = fmaf(s[p], t[dx + p], acc[dx][p]);
        }
    }

    // epilogue: 8-way atomic accumulation onto the zeroed leftover region
    const float inv = 1.0f / 81.0f;
    const int y = y0 + yr;
#pragma unroll
    for (int dx = 0; dx < NDY; dx++) {
        int d = disp_index(dyv, dx - RR);
        float* o = out + (((size_t)(3 * ND + d) * NH) + y) * NW + x0 + xg * PX;
#pragma unroll
        for (int p = 0; p < PX; p++)
            atomicAdd(o + p, acc[dx][p] * inv);
    }
}

extern "C" void kernel_launch(void* const* d_in, const int* in_sizes, int n_in,
                              void* d_out, int out_size) {
    const float* src = (const float*)d_in[0];
    const float* tgt = (const float*)d_in[1];
    float* out = (float*)d_out;

    cudaFuncSetAttribute(costvol_k1,
                         cudaFuncAttributeMaxDynamicSharedMemorySize, SMEM_BYTES);
    cudaFuncSetAttribute(costvol_k2,
                         cudaFuncAttributeMaxDynamicSharedMemorySize, SMEM2_BYTES);

    costvol_k1<<<K1_TILES, NTHREADS, SMEM_BYTES>>>(src, tgt, out);
    costvol_k2<<<K2_BLOCKS, NTHREADS, SMEM2_BYTES>>>(src, tgt, out);
}

// round 14
// speedup vs baseline: 1.1953x; 1.0727x over previous
#include <cuda_runtime.h>
#include <cstdint>

// Problem constants
#define RR 4
#define ND 81
#define NB 4
#define NC 128
#define NH 96
#define NW 160

// Tile geometry (proven core)
#define TX 32
#define YB 4
#define PX 4
#define XG 8
#define NDY 9
#define NTHREADS 288
#define CCHUNK 8
#define NCHUNK 16
#define TGT_W 40
#define TGT_H 12
#define TGT_TILE (CCHUNK*TGT_H*TGT_W)    // 3840 floats
#define SRC_TILE (CCHUNK*YB*TX)          // 1024 floats
#define BUF_FLOATS (TGT_TILE + SRC_TILE) // 4864
#define BUF_BYTES (BUF_FLOATS*4)         // 19456
#define SMEM_BYTES (3*BUF_BYTES)         // 58368
#define NQUADS (BUF_FLOATS/4)            // 1216
#define MAXSLOTS 5
#define CBYTES (CCHUNK*NH*NW*4)

// Schedule:
//  k1: 444 full tiles (tiles 0..443) = 148 SMs x occ 3, one perfect wave.
//  k2: leftover tiles 444..479, 4-way channel split -> 144 blocks, each
//      computes 32 channels (4 chunks) and stores partials to scratch.
//  k3: reduce 4 partials -> out (plain stores, deterministic).
#define K1_TILES 444
#define NLEFT 36
#define NPART 4
#define PART_STRIDE (NLEFT*ND*128)       // 373248 floats per partial
#define K3_QUADS (NLEFT*ND*YB*8)         // 93312 float4 outputs

__device__ float g_scratch[NPART * PART_STRIDE];   // ~6M floats (24MB), static

__device__ __forceinline__ int disp_index(int dyv, int dxv) {
    int ay = dyv < 0 ? -dyv : dyv;
    int ax = dxv < 0 ? -dxv : dxv;
    if ((ay | ax) == 0) return 0;
    if (ax == 0) return 1 + (ay - 1) * 20 + (dyv < 0 ? 0 : 1);
    if (ay == 0) return 1 + (ax - 1) * 20 + (dxv < 0 ? 2 : 3);
    int base = 1 + (ay - 1) * 20 + 4 + (ax - 1) * 4;
    if (dyv < 0 && dxv < 0) return base + 0;
    if (dyv > 0 && dxv > 0) return base + 1;
    if (dyv < 0 && dxv > 0) return base + 2;
    return base + 3;
}

__device__ __forceinline__ void cp_async16(uint32_t saddr, const void* gaddr, int sz) {
    asm volatile("cp.async.cg.shared.global [%0], [%1], 16, %2;\n"
                 :: "r"(saddr), "l"(gaddr), "r"(sz));
}
__device__ __forceinline__ void cp_commit() {
    asm volatile("cp.async.commit_group;\n" ::: "memory");
}

__device__ __forceinline__ void make_slots(int tid, int x0, int y0,
                                           uint32_t* goff, uint32_t& flags) {
    flags = 0;
#pragma unroll
    for (int k = 0; k < MAXSLOTS; k++) {
        int idx = tid + k * NTHREADS;
        goff[k] = 0;
        if (idx < NQUADS) {
            if (idx < TGT_TILE / 4) {
                int cc  = idx / (TGT_H * (TGT_W / 4));
                int rm  = idx % (TGT_H * (TGT_W / 4));
                int row = rm / (TGT_W / 4);
                int xq  = rm % (TGT_W / 4);
                int gy = y0 + row - RR;
                int gx = x0 + xq * 4 - RR;
                bool ok = ((unsigned)gy < NH) && ((unsigned)gx < NW);
                if (ok) goff[k] = (uint32_t)(((cc * NH + gy) * NW + gx) * 4);
                flags |= 1u << k;
                if (ok) flags |= 1u << (k + 8);
            } else {
                int q   = idx - TGT_TILE / 4;
                int cc  = q / (YB * TX / 4);
                int rm  = q % (YB * TX / 4);
                int ry  = rm / (TX / 4);
                int xq  = rm % (TX / 4);
                goff[k] = (uint32_t)(((cc * NH + y0 + ry) * NW + x0 + xq * 4) * 4);
                flags |= 1u << (k + 8);
            }
        }
    }
}

// ===================== Kernel 1: 444 full tiles =====================
__global__ __launch_bounds__(NTHREADS, 3)
void costvol_k1(const float* __restrict__ src,
                const float* __restrict__ tgt,
                float* __restrict__ out) {
    extern __shared__ __align__(16) float sm[];
    const int tid = threadIdx.x;
    const int bid = blockIdx.x;
    const uint32_t smem_base = (uint32_t)__cvta_generic_to_shared(&sm[0]);

    const int b   = bid / 120;
    const int rem = bid % 120;
    const int y0  = (rem / 5) * YB;
    const int x0  = (rem % 5) * TX;

    const char* srcB = (const char*)(src + (size_t)b * NC * NH * NW);
    const char* tgtB = (const char*)(tgt + (size_t)b * NC * NH * NW);

    uint32_t goff[MAXSLOTS];
    uint32_t flags;
    make_slots(tid, x0, y0, goff, flags);

    const int xg   = tid & (XG - 1);
    const int dyi  = (tid >> 3) % NDY;
    const int yr   = tid / (XG * NDY);
    const int dyv  = dyi - RR;
    const int trow = yr + dyi;
    const int t_off = trow * TGT_W + xg * PX;
    const int s_off = TGT_TILE + yr * TX + xg * PX;

    float acc[NDY][PX];
#pragma unroll
    for (int i = 0; i < NDY; i++)
#pragma unroll
        for (int p = 0; p < PX; p++) acc[i][p] = 0.0f;

    auto stage = [&](int bi) {
        const uint32_t bofs = (uint32_t)bi * BUF_BYTES;
#pragma unroll
        for (int k = 0; k < MAXSLOTS; k++) {
            if (k < MAXSLOTS - 1 || tid < NQUADS - (MAXSLOTS - 1) * NTHREADS) {
                const char* base = (flags >> k & 1) ? tgtB : srcB;
                int sz = (flags >> (k + 8) & 1) ? 16 : 0;
                cp_async16(smem_base + bofs + (uint32_t)(tid + k * NTHREADS) * 16,
                           base + goff[k], sz);
                goff[k] += CBYTES;
            }
        }
        cp_commit();
    };

    stage(0);
    stage(1);

#pragma unroll 1
    for (int ch = 0; ch < NCHUNK; ch++) {
        if (ch + 2 < NCHUNK)
            asm volatile("cp.async.wait_group 1;\n" ::: "memory");
        else
            asm volatile("cp.async.wait_group 0;\n" ::: "memory");
        __syncthreads();

        const float* bp = sm + (ch % 3) * BUF_FLOATS;
        const float* tb = bp + t_off;
        const float* sb = bp + s_off;
#pragma unroll
        for (int cc = 0; cc < CCHUNK; cc++) {
            float4 s4 = *(const float4*)(sb + cc * (YB * TX));
            const float4* tq = (const float4*)(tb + cc * (TGT_H * TGT_W));
            float4 t0 = tq[0], t1 = tq[1], t2 = tq[2];
            float s[PX] = {s4.x, s4.y, s4.z, s4.w};
            float t[12] = {t0.x, t0.y, t0.z, t0.w,
                           t1.x, t1.y, t1.z, t1.w,
                           t2.x, t2.y, t2.z, t2.w};
#pragma unroll
            for (int dx = 0; dx < NDY; dx++)
#pragma unroll
                for (int p = 0; p < PX; p++)
                    acc[dx][p] = fmaf(s[p], t[dx + p], acc[dx][p]);
        }

        if (ch + 2 < NCHUNK)
            stage((ch + 2) % 3);
    }

    const float inv = 1.0f / 81.0f;
    const int y = y0 + yr;
#pragma unroll
    for (int dx = 0; dx < NDY; dx++) {
        int d = disp_index(dyv, dx - RR);
        float* o = out + ((((size_t)b * ND + d) * NH) + y) * NW + x0 + xg * PX;
        float4 v = make_float4(acc[dx][0] * inv, acc[dx][1] * inv,
                               acc[dx][2] * inv, acc[dx][3] * inv);
        *(float4*)o = v;
    }
}

// ==== Kernel 2: 144 blocks (36 tiles x 4 channel-groups) -> scratch ====
__global__ __launch_bounds__(NTHREADS, 3)
void costvol_k2(const float* __restrict__ src,
                const float* __restrict__ tgt) {
    extern __shared__ __align__(16) float sm[];
    const int tid  = threadIdx.x;
    const int lt   = blockIdx.x >> 2;             // 0..35
    const int part = blockIdx.x & 3;              // 32-channel group

    const int rem = 84 + lt;                      // (444+lt)%120, b=3
    const int y0  = (rem / 5) * YB;
    const int x0  = (rem % 5) * TX;

    const char* srcB = (const char*)(src + (size_t)3 * NC * NH * NW)
                       + (size_t)part * 4 * CBYTES;
    const char* tgtB = (const char*)(tgt + (size_t)3 * NC * NH * NW)
                       + (size_t)part * 4 * CBYTES;

    uint32_t goff[MAXSLOTS];
    uint32_t flags;
    make_slots(tid, x0, y0, goff, flags);

    const uint32_t smem_base = (uint32_t)__cvta_generic_to_shared(&sm[0]);

    const int xg   = tid & (XG - 1);
    const int dyi  = (tid >> 3) % NDY;
    const int yr   = tid / (XG * NDY);
    const int dyv  = dyi - RR;
    const int trow = yr + dyi;
    const int t_off = trow * TGT_W + xg * PX;
    const int s_off = TGT_TILE + yr * TX + xg * PX;

    float acc[NDY][PX];
#pragma unroll
    for (int i = 0; i < NDY; i++)
#pragma unroll
        for (int p = 0; p < PX; p++) acc[i][p] = 0.0f;

    auto stage = [&](int bi) {
        const uint32_t bofs = (uint32_t)bi * BUF_BYTES;
#pragma unroll
        for (int k = 0; k < MAXSLOTS; k++) {
            if (k < MAXSLOTS - 1 || tid < NQUADS - (MAXSLOTS - 1) * NTHREADS) {
                const char* base = (flags >> k & 1) ? tgtB : srcB;
                int sz = (flags >> (k + 8) & 1) ? 16 : 0;
                cp_async16(smem_base + bofs + (uint32_t)(tid + k * NTHREADS) * 16,
                           base + goff[k], sz);
                goff[k] += CBYTES;
            }
        }
        cp_commit();
    };

    stage(0);
    stage(1);

#pragma unroll 1
    for (int ch = 0; ch < 4; ch++) {   // 4 chunks = 32 channels
        if (ch + 2 < 4)
            asm volatile("cp.async.wait_group 1;\n" ::: "memory");
        else
            asm volatile("cp.async.wait_group 0;\n" ::: "memory");
        __syncthreads();

        const float* bp = sm + (ch % 3) * BUF_FLOATS;
        const float* tb = bp + t_off;
        const float* sb = bp + s_off;
#pragma unroll
        for (int cc = 0; cc < CCHUNK; cc++) {
            float4 s4 = *(const float4*)(sb + cc * (YB * TX));
            const float4* tq = (const float4*)(tb + cc * (TGT_H * TGT_W));
            float4 t0 = tq[0], t1 = tq[1], t2 = tq[2];
            float s[PX] = {s4.x, s4.y, s4.z, s4.w};
            float t[12] = {t0.x, t0.y, t0.z, t0.w,
                           t1.x, t1.y, t1.z, t1.w,
                           t2.x, t2.y, t2.z, t2.w};
#pragma unroll
            for (int dx = 0; dx < NDY; dx++)
#pragma unroll
                for (int p = 0; p < PX; p++)
                    acc[dx][p] = fmaf(s[p], t[dx + p], acc[dx][p]);
        }

        if (ch + 2 < 4)
            stage((ch + 2) % 3);
    }

    // store partials: scratch[part][((lt*ND + d)*YB + yr)*32 + xg*4 ..]
    float* sc = g_scratch + (size_t)part * PART_STRIDE;
#pragma unroll
    for (int dx = 0; dx < NDY; dx++) {
        int d = disp_index(dyv, dx - RR);
        float* o = sc + (((size_t)lt * ND + d) * YB + yr) * 32 + xg * PX;
        *(float4*)o = make_float4(acc[dx][0], acc[dx][1], acc[dx][2], acc[dx][3]);
    }
}

// ============ Kernel 3: reduce 4 partials -> out (leftover tiles) ============
__global__ void costvol_k3(float* __restrict__ out) {
    int q = blockIdx.x * blockDim.x + threadIdx.x;
    if (q >= K3_QUADS) return;
    int xq = q & 7;
    int yr = (q >> 3) & 3;
    int d  = (q >> 5) % ND;
    int lt = q / (ND * 32);

    const float4* p0 = (const float4*)(g_scratch + (size_t)q * 4);
    const float4* p1 = (const float4*)(g_scratch + PART_STRIDE + (size_t)q * 4);
    const float4* p2 = (const float4*)(g_scratch + 2 * (size_t)PART_STRIDE + (size_t)q * 4);
    const float4* p3 = (const float4*)(g_scratch + 3 * (size_t)PART_STRIDE + (size_t)q * 4);
    float4 a = *p0, b = *p1, c = *p2, e = *p3;

    const float inv = 1.0f / 81.0f;
    float4 r = make_float4((((a.x + b.x) + c.x) + e.x) * inv,
                           (((a.y + b.y) + c.y) + e.y) * inv,
                           (((a.z + b.z) + c.z) + e.z) * inv,
                           (((a.w + b.w) + c.w) + e.w) * inv);

    int rem = 84 + lt;
    int y = (rem / 5) * YB + yr;
    int x = (rem % 5) * TX + xq * 4;
    float* o = out + (((size_t)(3 * ND + d) * NH) + y) * NW + x;
    *(float4*)o = r;
}

extern "C" void kernel_launch(void* const* d_in, const int* in_sizes, int n_in,
                              void* d_out, int out_size) {
    const float* src = (const float*)d_in[0];
    const float* tgt = (const float*)d_in[1];
    float* out = (float*)d_out;

    cudaFuncSetAttribute(costvol_k1,
                         cudaFuncAttributeMaxDynamicSharedMemorySize, SMEM_BYTES);
    cudaFuncSetAttribute(costvol_k2,
                         cudaFuncAttributeMaxDynamicSharedMemorySize, SMEM_BYTES);

    costvol_k1<<<K1_TILES, NTHREADS, SMEM_BYTES>>>(src, tgt, out);
    costvol_k2<<<NLEFT * NPART, NTHREADS, SMEM_BYTES>>>(src, tgt);
    costvol_k3<<<(K3_QUADS + 255) / 256, 256>>>(out);
}